// round 5
// baseline (speedup 1.0000x reference)
#include <cuda_runtime.h>
#include <cuda_bf16.h>
#include <stdint.h>
#include <math.h>

#define B_ 4
#define L_ 2048
#define D_ 1024
#define NBL (B_ * L_)

#define LOG2G  (-0.045803734f)          // log2(0.96875)
#define L2_1E4 (13.287712379549449f)    // log2(10000)

#define STAGE_BYTES 40960               // 4 tiles x (128 rows x 40 halves x 2B)
#define NSTAGE 3
#define GEMM_SMEM (STAGE_BYTES * NSTAGE)

// ------------------- global scratch (allocation-free rule) -------------------
__device__ __align__(16) __nv_bfloat16 g_Xh[NBL * D_], g_Xl[NBL * D_];
__device__ __align__(16) __nv_bfloat16 g_Wh[3][D_ * D_], g_Wl[3][D_ * D_];
__device__ __align__(16) __nv_bfloat16 g_Qh[NBL * D_], g_Ql[NBL * D_];
__device__ __align__(16) __nv_bfloat16 g_Kh[NBL * D_], g_Kl[NBL * D_];
__device__ __align__(16) __nv_bfloat16 g_Vh[NBL * D_], g_Vl[NBL * D_];
__device__ __align__(16) __nv_bfloat16 g_Th[NBL * D_], g_Tl[NBL * D_];  // V^T
__device__ __align__(16) __nv_bfloat16 g_Ah[(size_t)B_ * L_ * L_];
__device__ __align__(16) __nv_bfloat16 g_Al[(size_t)B_ * L_ * L_];
__device__ __align__(16) float4 g_xt[(size_t)L_ * (D_ / 2)];  // cQ,sQ,cK,sK

// ------------------------------- helpers -------------------------------------
__device__ __forceinline__ uint32_t smem_u32(const void* p) {
    uint32_t a;
    asm("{ .reg .u64 t; cvta.to.shared.u64 t, %1; cvt.u32.u64 %0, t; }"
        : "=r"(a) : "l"(p));
    return a;
}

__device__ __forceinline__ void ldm4(uint32_t* r, uint32_t a) {
    asm volatile("ldmatrix.sync.aligned.m8n8.x4.shared.b16 {%0,%1,%2,%3}, [%4];"
                 : "=r"(r[0]), "=r"(r[1]), "=r"(r[2]), "=r"(r[3]) : "r"(a));
}

__device__ __forceinline__ void mma_bf16(float* c, const uint32_t* a, const uint32_t* b) {
    asm volatile(
        "mma.sync.aligned.m16n8k16.row.col.f32.bf16.bf16.f32 "
        "{%0,%1,%2,%3}, {%4,%5,%6,%7}, {%8,%9}, {%0,%1,%2,%3};"
        : "+f"(c[0]), "+f"(c[1]), "+f"(c[2]), "+f"(c[3])
        : "r"(a[0]), "r"(a[1]), "r"(a[2]), "r"(a[3]), "r"(b[0]), "r"(b[1]));
}

__device__ __forceinline__ void cp16(uint32_t dst, const void* src) {
    asm volatile("cp.async.cg.shared.global [%0], [%1], 16;" :: "r"(dst), "l"(src));
}
__device__ __forceinline__ void cp_commit() {
    asm volatile("cp.async.commit_group;" ::: "memory");
}
template <int N>
__device__ __forceinline__ void cp_wait() {
    asm volatile("cp.async.wait_group %0;" :: "n"(N) : "memory");
}

// bf16 hi/lo split of two floats, packed as bf16x2 words
__device__ __forceinline__ void split2(float a, float b, uint32_t& hi, uint32_t& lo) {
    __nv_bfloat16 ha = __float2bfloat16(a);
    __nv_bfloat16 hb = __float2bfloat16(b);
    __nv_bfloat16 la = __float2bfloat16(a - __bfloat162float(ha));
    __nv_bfloat16 lb = __float2bfloat16(b - __bfloat162float(hb));
    __nv_bfloat162 H;  H.x = ha; H.y = hb;
    __nv_bfloat162 Lo; Lo.x = la; Lo.y = lb;
    hi = *reinterpret_cast<uint32_t*>(&H);
    lo = *reinterpret_cast<uint32_t*>(&Lo);
}

// async-copy one 128x32 bf16 tile, gmem(stride ld) -> smem stage (stride 40)
__device__ __forceinline__ void cpa_tile(uint32_t sbase,
                                         const __nv_bfloat16* __restrict__ g,
                                         int ld, int t) {
#pragma unroll
    for (int it = 0; it < 2; ++it) {
        int idx = t + it * 256;
        int r = idx >> 2, sg = (idx & 3) << 3;
        cp16(sbase + (uint32_t)(r * 80 + sg * 2),
             g + (size_t)r * ld + sg);
    }
}

// issue all 4 tiles of one chunk into a stage, then commit
__device__ __forceinline__ void issue_chunk(
    uint32_t stage_base,
    const __nv_bfloat16* __restrict__ Agh, const __nv_bfloat16* __restrict__ Agl,
    const __nv_bfloat16* __restrict__ Bgh, const __nv_bfloat16* __restrict__ Bgl,
    int lda, int ldb, int k0, int t) {
    cpa_tile(stage_base,         Agh + k0, lda, t);
    cpa_tile(stage_base + 10240, Agl + k0, lda, t);
    cpa_tile(stage_base + 20480, Bgh + k0, ldb, t);
    cpa_tile(stage_base + 30720, Bgl + k0, ldb, t);
    cp_commit();
}

// -------------------- CTA 128x128 GEMM mainloop (bf16 split) -----------------
// 3-stage cp.async pipeline. acc per warp: [m 0..1][n 0..7][c0..3]
__device__ __forceinline__ void gemm_loop(
    float acc[2][8][4],
    const __nv_bfloat16* __restrict__ Agh, const __nv_bfloat16* __restrict__ Agl,
    const __nv_bfloat16* __restrict__ Bgh, const __nv_bfloat16* __restrict__ Bgl,
    int lda, int ldb, int nchunks, uint32_t smb, int t) {
    const int lane = t & 31, w = t >> 5;
    const int wm0 = (w >> 1) << 5;   // warp m offset (0,32,64,96)
    const int wn0 = (w & 1) << 6;    // warp n offset (0,64)

    // ldmatrix per-thread offsets within a stage (bytes)
    const int arow = wm0 + (lane & 15);
    const int acol = (lane >> 4) << 3;
    const uint32_t aOffH = (uint32_t)(arow * 40 + acol) * 2;
    const int brow = wn0 + ((lane >> 4) << 3) + (lane & 7);
    const int bcol = ((lane >> 3) & 1) << 3;
    const uint32_t bOffH = 20480u + (uint32_t)(brow * 40 + bcol) * 2;

    // prologue: fill stages 0,1
    issue_chunk(smb, Agh, Agl, Bgh, Bgl, lda, ldb, 0, t);
    if (nchunks > 1)
        issue_chunk(smb + STAGE_BYTES, Agh, Agl, Bgh, Bgl, lda, ldb, 32, t);

    int stage = 0;
    for (int ch = 0; ch < nchunks; ++ch) {
        if (ch + 2 < nchunks) {
            int ns = stage + 2; if (ns >= NSTAGE) ns -= NSTAGE;
            issue_chunk(smb + ns * STAGE_BYTES, Agh, Agl, Bgh, Bgl,
                        lda, ldb, (ch + 2) * 32, t);
            cp_wait<2>();
        } else if (ch + 1 < nchunks) {
            cp_wait<1>();
        } else {
            cp_wait<0>();
        }
        __syncthreads();

        const uint32_t sb = smb + stage * STAGE_BYTES;
        const uint32_t aH = sb + aOffH;
        const uint32_t aL = aH + 10240;
        const uint32_t bH = sb + bOffH;
        const uint32_t bL = bH + 10240;

#pragma unroll
        for (int kk = 0; kk < 2; ++kk) {
            const uint32_t kb = kk * 32;  // 16 halves = 32 bytes
            uint32_t af[2][2][4], bf[2][8][2];
#pragma unroll
            for (int i = 0; i < 2; ++i) {
                ldm4(af[0][i], aH + i * 16 * 80 + kb);
                ldm4(af[1][i], aL + i * 16 * 80 + kb);
            }
#pragma unroll
            for (int jp = 0; jp < 4; ++jp) {
                uint32_t tp[4];
                ldm4(tp, bH + jp * 16 * 80 + kb);
                bf[0][2 * jp][0] = tp[0]; bf[0][2 * jp][1] = tp[1];
                bf[0][2 * jp + 1][0] = tp[2]; bf[0][2 * jp + 1][1] = tp[3];
                ldm4(tp, bL + jp * 16 * 80 + kb);
                bf[1][2 * jp][0] = tp[0]; bf[1][2 * jp][1] = tp[1];
                bf[1][2 * jp + 1][0] = tp[2]; bf[1][2 * jp + 1][1] = tp[3];
            }
#pragma unroll
            for (int i = 0; i < 2; ++i)
#pragma unroll
                for (int j = 0; j < 8; ++j) {
                    mma_bf16(acc[i][j], af[0][i], bf[0][j]);
                    mma_bf16(acc[i][j], af[0][i], bf[1][j]);
                    mma_bf16(acc[i][j], af[1][i], bf[0][j]);
                }
        }
        __syncthreads();
        if (++stage >= NSTAGE) stage = 0;
    }
}

// ------------------------------- prep kernels --------------------------------
__global__ __launch_bounds__(256) void cvt_x_kernel(const float* __restrict__ X) {
    size_t i = ((size_t)blockIdx.x * 256 + threadIdx.x) * 4;
    float4 v = *reinterpret_cast<const float4*>(X + i);
    uint32_t h0, l0, h1, l1;
    split2(v.x, v.y, h0, l0);
    split2(v.z, v.w, h1, l1);
    uint2 H; H.x = h0; H.y = h1;
    uint2 L; L.x = l0; L.y = l1;
    *reinterpret_cast<uint2*>(g_Xh + i) = H;
    *reinterpret_cast<uint2*>(g_Xl + i) = L;
}

// transpose + split W[k][n] -> Wt[n][k]
template <int S>
__global__ __launch_bounds__(256) void wt_kernel(const float* __restrict__ W) {
    __shared__ float ts[32][33];
    int n0 = blockIdx.x * 32, k0 = blockIdx.y * 32;
    int tx = threadIdx.x & 31, ty = threadIdx.x >> 5;
#pragma unroll
    for (int j = 0; j < 4; ++j)
        ts[ty + 8 * j][tx] = W[(size_t)(k0 + ty + 8 * j) * D_ + n0 + tx];
    __syncthreads();
#pragma unroll
    for (int j = 0; j < 4; ++j) {
        float v = ts[tx][ty + 8 * j];
        __nv_bfloat16 h = __float2bfloat16(v);
        __nv_bfloat16 l = __float2bfloat16(v - __bfloat162float(h));
        size_t o = (size_t)(n0 + ty + 8 * j) * D_ + k0 + tx;
        g_Wh[S][o] = h;
        g_Wl[S][o] = l;
    }
}

// transpose V[l][d] -> Vt[d][l] (hi and lo)
__global__ __launch_bounds__(256) void vt_kernel() {
    __shared__ __nv_bfloat16 ts[32][34];
    int b = blockIdx.z;
    int l0 = blockIdx.x * 32, d0 = blockIdx.y * 32;
    int tx = threadIdx.x & 31, ty = threadIdx.x >> 5;
#pragma unroll
    for (int a = 0; a < 2; ++a) {
        const __nv_bfloat16* s = (a ? g_Vl : g_Vh) + (size_t)b * L_ * D_;
        __nv_bfloat16* d = (a ? g_Tl : g_Th) + (size_t)b * L_ * D_;
        if (a) __syncthreads();
#pragma unroll
        for (int j = 0; j < 4; ++j)
            ts[ty + 8 * j][tx] = s[(size_t)(l0 + ty + 8 * j) * D_ + d0 + tx];
        __syncthreads();
#pragma unroll
        for (int j = 0; j < 4; ++j)
            d[(size_t)(d0 + ty + 8 * j) * L_ + l0 + tx] = ts[tx][ty + 8 * j];
    }
}

// precompute xPos rotation table
__global__ __launch_bounds__(256) void xt_kernel() {
    int idx = blockIdx.x * 256 + threadIdx.x;  // pos*512 + cp
    int pos = idx >> 9;
    int cp = idx & 511;
    float sv = (2.0f * cp + 409.6f) * (1.0f / 1433.6f);
    float sc = exp2f((float)pos * (1.0f / 512.0f) * log2f(sv));
    float invf = exp2f(-(float)cp * (L2_1E4 / 512.0f));
    float s, c;
    sincosf((float)pos * invf, &s, &c);
    g_xt[idx] = make_float4(c * sc, s * sc, c / sc, s / sc);
}

// ----------------------- projection GEMMs (Q / K / V) ------------------------
template <int MODE>  // 0=Q, 1=K, 2=V
__global__ __launch_bounds__(256) void proj_mm() {
    extern __shared__ char dsm[];
    uint32_t smb = smem_u32(dsm);
    float acc[2][8][4] = {};
    const int t = threadIdx.x;
    const int n0 = blockIdx.x << 7, m0 = blockIdx.y << 7;

    gemm_loop(acc,
              g_Xh + (size_t)m0 * D_, g_Xl + (size_t)m0 * D_,
              g_Wh[MODE] + (size_t)n0 * D_, g_Wl[MODE] + (size_t)n0 * D_,
              D_, D_, D_ / 32, smb, t);

    const int lane = t & 31, w = t >> 5;
    const int wm0 = (w >> 1) << 5, wn0 = (w & 1) << 6;
    const int rf = lane >> 2, cf = (lane & 3) << 1;
    __nv_bfloat16* dh = (MODE == 0) ? g_Qh : (MODE == 1 ? g_Kh : g_Vh);
    __nv_bfloat16* dl = (MODE == 0) ? g_Ql : (MODE == 1 ? g_Kl : g_Vl);

#pragma unroll
    for (int i = 0; i < 2; ++i)
#pragma unroll
        for (int hf = 0; hf < 2; ++hf) {
            int row = m0 + wm0 + i * 16 + rf + hf * 8;
            int pos = row & (L_ - 1);
#pragma unroll
            for (int j = 0; j < 8; ++j) {
                int col = n0 + wn0 + j * 8 + cf;
                float x0 = acc[i][j][hf * 2], x1 = acc[i][j][hf * 2 + 1];
                float y0, y1;
                if (MODE == 2) {
                    y0 = x0; y1 = x1;
                } else {
                    float4 tb = g_xt[(size_t)pos * 512 + (col >> 1)];
                    float c = (MODE == 0) ? tb.x : tb.z;
                    float s = (MODE == 0) ? tb.y : tb.w;
                    y0 = x0 * c - x1 * s;
                    y1 = x1 * c + x0 * s;
                }
                uint32_t h, l;
                split2(y0, y1, h, l);
                *reinterpret_cast<uint32_t*>(dh + (size_t)row * D_ + col) = h;
                *reinterpret_cast<uint32_t*>(dl + (size_t)row * D_ + col) = l;
            }
        }
}

// -------------------- A = (Q K^T) * decay, bf16 hi/lo ------------------------
__global__ __launch_bounds__(256) void qk_mm() {
    extern __shared__ char dsm[];
    uint32_t smb = smem_u32(dsm);
    __shared__ float pw[128], ipw[128];
    const int t = threadIdx.x;
    const int b = blockIdx.z;
    const int m0 = blockIdx.x << 7;  // keys
    const int n0 = blockIdx.y << 7;  // queries
    if (m0 >= n0 + 128) return;      // strictly-causal tile: never read by av

    if (t < 128) {
        pw[t] = exp2f((float)t * LOG2G);
        ipw[t] = exp2f(-(float)t * LOG2G);
    }

    float acc[2][8][4] = {};
    gemm_loop(acc,
              g_Qh + (size_t)(b * L_ + n0) * D_, g_Ql + (size_t)(b * L_ + n0) * D_,
              g_Kh + (size_t)(b * L_ + m0) * D_, g_Kl + (size_t)(b * L_ + m0) * D_,
              D_, D_, D_ / 32, smb, t);

    const int lane = t & 31, w = t >> 5;
    const int wm0 = (w >> 1) << 5, wn0 = (w & 1) << 6;
    const int rf = lane >> 2, cf = (lane & 3) << 1;
    const float base = exp2f((float)(n0 - m0) * LOG2G);
    __nv_bfloat16* Ah = g_Ah + (size_t)b * L_ * L_;
    __nv_bfloat16* Al = g_Al + (size_t)b * L_ * L_;

#pragma unroll
    for (int i = 0; i < 2; ++i)
#pragma unroll
        for (int hf = 0; hf < 2; ++hf) {
            int r = wm0 + i * 16 + rf + hf * 8;
            int gn = n0 + r;
            float bp = base * pw[r];
#pragma unroll
            for (int j = 0; j < 8; ++j) {
                int c = wn0 + j * 8 + cf;
                int gm = m0 + c;
                float v0 = (gm <= gn) ? acc[i][j][hf * 2] * (bp * ipw[c]) : 0.f;
                float v1 = (gm + 1 <= gn) ? acc[i][j][hf * 2 + 1] * (bp * ipw[c + 1]) : 0.f;
                uint32_t h, l;
                split2(v0, v1, h, l);
                *reinterpret_cast<uint32_t*>(Ah + (size_t)gn * L_ + gm) = h;
                *reinterpret_cast<uint32_t*>(Al + (size_t)gn * L_ + gm) = l;
            }
        }
}

// ------------------------------ out = A @ V ----------------------------------
__global__ __launch_bounds__(256) void av_mm(float* __restrict__ out) {
    extern __shared__ char dsm[];
    uint32_t smb = smem_u32(dsm);
    const int t = threadIdx.x;
    const int b = blockIdx.z;
    const int j0 = blockIdx.x << 7;  // output features
    const int n0 = blockIdx.y << 7;  // rows
    const int chunks = (blockIdx.y + 1) * 4;  // causal K-extent / 32

    float acc[2][8][4] = {};
    gemm_loop(acc,
              g_Ah + ((size_t)b * L_ + n0) * L_, g_Al + ((size_t)b * L_ + n0) * L_,
              g_Th + (size_t)b * L_ * D_ + (size_t)j0 * L_,
              g_Tl + (size_t)b * L_ * D_ + (size_t)j0 * L_,
              L_, L_, chunks, smb, t);

    const int lane = t & 31, w = t >> 5;
    const int wm0 = (w >> 1) << 5, wn0 = (w & 1) << 6;
    const int rf = lane >> 2, cf = (lane & 3) << 1;

#pragma unroll
    for (int i = 0; i < 2; ++i)
#pragma unroll
        for (int hf = 0; hf < 2; ++hf) {
            int row = n0 + wm0 + i * 16 + rf + hf * 8;
#pragma unroll
            for (int j = 0; j < 8; ++j) {
                int col = j0 + wn0 + j * 8 + cf;
                float2 v;
                v.x = acc[i][j][hf * 2];
                v.y = acc[i][j][hf * 2 + 1];
                *reinterpret_cast<float2*>(out + ((size_t)(b * L_ + row)) * D_ + col) = v;
            }
        }
}

// -----------------------------------------------------------------------------
extern "C" void kernel_launch(void* const* d_in, const int* in_sizes, int n_in,
                              void* d_out, int out_size) {
    const float* X = (const float*)d_in[0];
    const float* WQ = (const float*)d_in[1];
    const float* WK = (const float*)d_in[2];
    const float* WV = (const float*)d_in[3];
    float* out = (float*)d_out;

    static int inited = 0;
    if (!inited) {
        cudaFuncSetAttribute(proj_mm<0>, cudaFuncAttributeMaxDynamicSharedMemorySize, GEMM_SMEM);
        cudaFuncSetAttribute(proj_mm<1>, cudaFuncAttributeMaxDynamicSharedMemorySize, GEMM_SMEM);
        cudaFuncSetAttribute(proj_mm<2>, cudaFuncAttributeMaxDynamicSharedMemorySize, GEMM_SMEM);
        cudaFuncSetAttribute(qk_mm, cudaFuncAttributeMaxDynamicSharedMemorySize, GEMM_SMEM);
        cudaFuncSetAttribute(av_mm, cudaFuncAttributeMaxDynamicSharedMemorySize, GEMM_SMEM);
        inited = 1;
    }

    cvt_x_kernel<<<(NBL * D_) / 1024, 256>>>(X);
    dim3 wg(32, 32);
    wt_kernel<0><<<wg, 256>>>(WQ);
    wt_kernel<1><<<wg, 256>>>(WK);
    wt_kernel<2><<<wg, 256>>>(WV);
    xt_kernel<<<(L_ * 512) / 256, 256>>>();

    proj_mm<0><<<dim3(8, 64), 256, GEMM_SMEM>>>();
    proj_mm<1><<<dim3(8, 64), 256, GEMM_SMEM>>>();
    proj_mm<2><<<dim3(8, 64), 256, GEMM_SMEM>>>();
    vt_kernel<<<dim3(64, 32, B_), 256>>>();

    qk_mm<<<dim3(16, 16, B_), 256, GEMM_SMEM>>>();
    av_mm<<<dim3(8, 16, B_), 256, GEMM_SMEM>>>(out);
}

// round 6
// speedup vs baseline: 1.3786x; 1.3786x over previous
#include <cuda_runtime.h>
#include <cuda_bf16.h>
#include <cuda_fp16.h>
#include <stdint.h>
#include <math.h>

#define B_ 4
#define L_ 2048
#define D_ 1024
#define NBL (B_ * L_)
#define WIN 512                         // decay truncation window (multiple of 128)

#define LOG2G  (-0.045803734f)          // log2(0.96875)
#define L2_1E4 (13.287712379549449f)    // log2(10000)

// ------------------- global scratch (allocation-free rule) -------------------
__device__ __align__(16) __nv_bfloat16 g_Xh[NBL * D_], g_Xl[NBL * D_];
__device__ __align__(16) __nv_bfloat16 g_Wh[3][D_ * D_], g_Wl[3][D_ * D_];
__device__ __align__(16) __nv_bfloat16 g_Qh[NBL * D_], g_Ql[NBL * D_];
__device__ __align__(16) __nv_bfloat16 g_Kh[NBL * D_], g_Kl[NBL * D_];
__device__ __align__(16) __nv_bfloat16 g_Vh[NBL * D_], g_Vl[NBL * D_];
__device__ __align__(16) __half        g_Th[NBL * D_], g_Tl[NBL * D_];  // V^T fp16 split
__device__ __align__(16) __half        g_A[(size_t)B_ * L_ * L_];       // A fp16 single
__device__ __align__(16) float4 g_xt[(size_t)L_ * (D_ / 2)];  // cQ,sQ,cK,sK

// ------------------------------- helpers -------------------------------------
__device__ __forceinline__ uint32_t smem_u32(const void* p) {
    uint32_t a;
    asm("{ .reg .u64 t; cvta.to.shared.u64 t, %1; cvt.u32.u64 %0, t; }"
        : "=r"(a) : "l"(p));
    return a;
}

__device__ __forceinline__ void ldm4(uint32_t* r, uint32_t a) {
    asm volatile("ldmatrix.sync.aligned.m8n8.x4.shared.b16 {%0,%1,%2,%3}, [%4];"
                 : "=r"(r[0]), "=r"(r[1]), "=r"(r[2]), "=r"(r[3]) : "r"(a));
}

__device__ __forceinline__ void mma_bf16(float* c, const uint32_t* a, const uint32_t* b) {
    asm volatile(
        "mma.sync.aligned.m16n8k16.row.col.f32.bf16.bf16.f32 "
        "{%0,%1,%2,%3}, {%4,%5,%6,%7}, {%8,%9}, {%0,%1,%2,%3};"
        : "+f"(c[0]), "+f"(c[1]), "+f"(c[2]), "+f"(c[3])
        : "r"(a[0]), "r"(a[1]), "r"(a[2]), "r"(a[3]), "r"(b[0]), "r"(b[1]));
}

__device__ __forceinline__ void mma_f16(float* c, const uint32_t* a, const uint32_t* b) {
    asm volatile(
        "mma.sync.aligned.m16n8k16.row.col.f32.f16.f16.f32 "
        "{%0,%1,%2,%3}, {%4,%5,%6,%7}, {%8,%9}, {%0,%1,%2,%3};"
        : "+f"(c[0]), "+f"(c[1]), "+f"(c[2]), "+f"(c[3])
        : "r"(a[0]), "r"(a[1]), "r"(a[2]), "r"(a[3]), "r"(b[0]), "r"(b[1]));
}

// bf16 hi/lo split of two floats, packed as bf16x2 words
__device__ __forceinline__ void split2(float a, float b, uint32_t& hi, uint32_t& lo) {
    __nv_bfloat16 ha = __float2bfloat16(a);
    __nv_bfloat16 hb = __float2bfloat16(b);
    __nv_bfloat16 la = __float2bfloat16(a - __bfloat162float(ha));
    __nv_bfloat16 lb = __float2bfloat16(b - __bfloat162float(hb));
    __nv_bfloat162 H;  H.x = ha; H.y = hb;
    __nv_bfloat162 Lo; Lo.x = la; Lo.y = lb;
    hi = *reinterpret_cast<uint32_t*>(&H);
    lo = *reinterpret_cast<uint32_t*>(&Lo);
}

// copy 128 rows x 32 cols (16-bit elems), gmem(stride ld) -> smem(stride 40)
__device__ __forceinline__ void ldtile(uint16_t* s, const uint16_t* __restrict__ g,
                                       int ld, int t) {
#pragma unroll
    for (int it = 0; it < 2; ++it) {
        int idx = t + it * 256;
        int r = idx >> 2, sg = (idx & 3) << 3;
        *reinterpret_cast<float4*>(s + r * 40 + sg) =
            *reinterpret_cast<const float4*>(g + (size_t)r * ld + sg);
    }
}

// -------------------- CTA 128x128 GEMM mainloop (bf16 split) -----------------
__device__ __forceinline__ void gemm_loop(
    float acc[2][8][4],
    const __nv_bfloat16* __restrict__ Agh, const __nv_bfloat16* __restrict__ Agl,
    const __nv_bfloat16* __restrict__ Bgh, const __nv_bfloat16* __restrict__ Bgl,
    int lda, int ldb, int nchunks, __nv_bfloat16* sm, int t) {
    uint16_t* sAh = (uint16_t*)sm;
    uint16_t* sAl = (uint16_t*)sm + 5120;
    uint16_t* sBh = (uint16_t*)sm + 10240;
    uint16_t* sBl = (uint16_t*)sm + 15360;

    const int lane = t & 31, w = t >> 5;
    const int wm0 = (w >> 1) << 5;
    const int wn0 = (w & 1) << 6;

    const int arow = wm0 + (lane & 15);
    const int acol = (lane >> 4) << 3;
    const uint32_t aH = smem_u32(sAh) + (uint32_t)(arow * 40 + acol) * 2;
    const uint32_t aL = aH + 10240;
    const int brow = wn0 + ((lane >> 4) << 3) + (lane & 7);
    const int bcol = ((lane >> 3) & 1) << 3;
    const uint32_t bH = smem_u32(sBh) + (uint32_t)(brow * 40 + bcol) * 2;
    const uint32_t bL = bH + 10240;

    for (int ch = 0; ch < nchunks; ++ch) {
        const int k0 = ch * 32;
        ldtile(sAh, (const uint16_t*)Agh + k0, lda, t);
        ldtile(sAl, (const uint16_t*)Agl + k0, lda, t);
        ldtile(sBh, (const uint16_t*)Bgh + k0, ldb, t);
        ldtile(sBl, (const uint16_t*)Bgl + k0, ldb, t);
        __syncthreads();

#pragma unroll
        for (int kk = 0; kk < 2; ++kk) {
            const uint32_t kb = kk * 32;
            uint32_t af[2][2][4], bf[2][8][2];
#pragma unroll
            for (int i = 0; i < 2; ++i) {
                ldm4(af[0][i], aH + i * 16 * 80 + kb);
                ldm4(af[1][i], aL + i * 16 * 80 + kb);
            }
#pragma unroll
            for (int jp = 0; jp < 4; ++jp) {
                uint32_t tp[4];
                ldm4(tp, bH + jp * 16 * 80 + kb);
                bf[0][2 * jp][0] = tp[0]; bf[0][2 * jp][1] = tp[1];
                bf[0][2 * jp + 1][0] = tp[2]; bf[0][2 * jp + 1][1] = tp[3];
                ldm4(tp, bL + jp * 16 * 80 + kb);
                bf[1][2 * jp][0] = tp[0]; bf[1][2 * jp][1] = tp[1];
                bf[1][2 * jp + 1][0] = tp[2]; bf[1][2 * jp + 1][1] = tp[3];
            }
#pragma unroll
            for (int i = 0; i < 2; ++i)
#pragma unroll
                for (int j = 0; j < 8; ++j) {
                    mma_bf16(acc[i][j], af[0][i], bf[0][j]);
                    mma_bf16(acc[i][j], af[0][i], bf[1][j]);
                    mma_bf16(acc[i][j], af[1][i], bf[0][j]);
                }
        }
        __syncthreads();
    }
}

// ------------- av mainloop: A fp16 single x V^T fp16 split (2 MMA) -----------
__device__ __forceinline__ void gemm_loop_av(
    float acc[2][8][4],
    const __half* __restrict__ Ag,
    const __half* __restrict__ Bgh, const __half* __restrict__ Bgl,
    int lda, int ldb, int nchunks, __half* sm, int t) {
    uint16_t* sA  = (uint16_t*)sm;
    uint16_t* sBh = (uint16_t*)sm + 5120;
    uint16_t* sBl = (uint16_t*)sm + 10240;

    const int lane = t & 31, w = t >> 5;
    const int wm0 = (w >> 1) << 5;
    const int wn0 = (w & 1) << 6;

    const int arow = wm0 + (lane & 15);
    const int acol = (lane >> 4) << 3;
    const uint32_t aA = smem_u32(sA) + (uint32_t)(arow * 40 + acol) * 2;
    const int brow = wn0 + ((lane >> 4) << 3) + (lane & 7);
    const int bcol = ((lane >> 3) & 1) << 3;
    const uint32_t bH = smem_u32(sBh) + (uint32_t)(brow * 40 + bcol) * 2;
    const uint32_t bL = bH + 10240;

    for (int ch = 0; ch < nchunks; ++ch) {
        const int k0 = ch * 32;
        ldtile(sA,  (const uint16_t*)Ag + k0, lda, t);
        ldtile(sBh, (const uint16_t*)Bgh + k0, ldb, t);
        ldtile(sBl, (const uint16_t*)Bgl + k0, ldb, t);
        __syncthreads();

#pragma unroll
        for (int kk = 0; kk < 2; ++kk) {
            const uint32_t kb = kk * 32;
            uint32_t af[2][4], bf[2][8][2];
#pragma unroll
            for (int i = 0; i < 2; ++i)
                ldm4(af[i], aA + i * 16 * 80 + kb);
#pragma unroll
            for (int jp = 0; jp < 4; ++jp) {
                uint32_t tp[4];
                ldm4(tp, bH + jp * 16 * 80 + kb);
                bf[0][2 * jp][0] = tp[0]; bf[0][2 * jp][1] = tp[1];
                bf[0][2 * jp + 1][0] = tp[2]; bf[0][2 * jp + 1][1] = tp[3];
                ldm4(tp, bL + jp * 16 * 80 + kb);
                bf[1][2 * jp][0] = tp[0]; bf[1][2 * jp][1] = tp[1];
                bf[1][2 * jp + 1][0] = tp[2]; bf[1][2 * jp + 1][1] = tp[3];
            }
#pragma unroll
            for (int i = 0; i < 2; ++i)
#pragma unroll
                for (int j = 0; j < 8; ++j) {
                    mma_f16(acc[i][j], af[i], bf[0][j]);
                    mma_f16(acc[i][j], af[i], bf[1][j]);
                }
        }
        __syncthreads();
    }
}

// ------------------------------- prep kernels --------------------------------
__global__ __launch_bounds__(256) void cvt_x_kernel(const float* __restrict__ X) {
    size_t i = ((size_t)blockIdx.x * 256 + threadIdx.x) * 4;
    float4 v = *reinterpret_cast<const float4*>(X + i);
    uint32_t h0, l0, h1, l1;
    split2(v.x, v.y, h0, l0);
    split2(v.z, v.w, h1, l1);
    uint2 H; H.x = h0; H.y = h1;
    uint2 L; L.x = l0; L.y = l1;
    *reinterpret_cast<uint2*>(g_Xh + i) = H;
    *reinterpret_cast<uint2*>(g_Xl + i) = L;
}

// transpose + split W[k][n] -> Wt[n][k]
template <int S>
__global__ __launch_bounds__(256) void wt_kernel(const float* __restrict__ W) {
    __shared__ float ts[32][33];
    int n0 = blockIdx.x * 32, k0 = blockIdx.y * 32;
    int tx = threadIdx.x & 31, ty = threadIdx.x >> 5;
#pragma unroll
    for (int j = 0; j < 4; ++j)
        ts[ty + 8 * j][tx] = W[(size_t)(k0 + ty + 8 * j) * D_ + n0 + tx];
    __syncthreads();
#pragma unroll
    for (int j = 0; j < 4; ++j) {
        float v = ts[tx][ty + 8 * j];
        __nv_bfloat16 h = __float2bfloat16(v);
        __nv_bfloat16 l = __float2bfloat16(v - __bfloat162float(h));
        size_t o = (size_t)(n0 + ty + 8 * j) * D_ + k0 + tx;
        g_Wh[S][o] = h;
        g_Wl[S][o] = l;
    }
}

// transpose V (bf16 split) -> V^T fp16 hi/lo
__global__ __launch_bounds__(256) void vt_kernel() {
    __shared__ float ts[32][33];
    int b = blockIdx.z;
    int l0 = blockIdx.x * 32, d0 = blockIdx.y * 32;
    int tx = threadIdx.x & 31, ty = threadIdx.x >> 5;
    const __nv_bfloat16* vh = g_Vh + (size_t)b * L_ * D_;
    const __nv_bfloat16* vl = g_Vl + (size_t)b * L_ * D_;
    __half* th = g_Th + (size_t)b * L_ * D_;
    __half* tl = g_Tl + (size_t)b * L_ * D_;
#pragma unroll
    for (int j = 0; j < 4; ++j) {
        size_t o = (size_t)(l0 + ty + 8 * j) * D_ + d0 + tx;
        ts[ty + 8 * j][tx] = __bfloat162float(vh[o]) + __bfloat162float(vl[o]);
    }
    __syncthreads();
#pragma unroll
    for (int j = 0; j < 4; ++j) {
        float v = ts[tx][ty + 8 * j];
        __half h = __float2half_rn(v);
        __half l = __float2half_rn(v - __half2float(h));
        size_t o = (size_t)(d0 + ty + 8 * j) * L_ + l0 + tx;
        th[o] = h;
        tl[o] = l;
    }
}

// precompute xPos rotation table
__global__ __launch_bounds__(256) void xt_kernel() {
    int idx = blockIdx.x * 256 + threadIdx.x;  // pos*512 + cp
    int pos = idx >> 9;
    int cp = idx & 511;
    float sv = (2.0f * cp + 409.6f) * (1.0f / 1433.6f);
    float sc = exp2f((float)pos * (1.0f / 512.0f) * log2f(sv));
    float invf = exp2f(-(float)cp * (L2_1E4 / 512.0f));
    float s, c;
    sincosf((float)pos * invf, &s, &c);
    g_xt[idx] = make_float4(c * sc, s * sc, c / sc, s / sc);
}

// ----------------------- projection GEMMs (Q / K / V) ------------------------
template <int MODE>  // 0=Q, 1=K, 2=V
__global__ __launch_bounds__(256) void proj_mm() {
    __shared__ __nv_bfloat16 sm[20480];
    float acc[2][8][4] = {};
    const int t = threadIdx.x;
    const int n0 = blockIdx.x << 7, m0 = blockIdx.y << 7;

    gemm_loop(acc,
              g_Xh + (size_t)m0 * D_, g_Xl + (size_t)m0 * D_,
              g_Wh[MODE] + (size_t)n0 * D_, g_Wl[MODE] + (size_t)n0 * D_,
              D_, D_, D_ / 32, sm, t);

    const int lane = t & 31, w = t >> 5;
    const int wm0 = (w >> 1) << 5, wn0 = (w & 1) << 6;
    const int rf = lane >> 2, cf = (lane & 3) << 1;
    __nv_bfloat16* dh = (MODE == 0) ? g_Qh : (MODE == 1 ? g_Kh : g_Vh);
    __nv_bfloat16* dl = (MODE == 0) ? g_Ql : (MODE == 1 ? g_Kl : g_Vl);

#pragma unroll
    for (int i = 0; i < 2; ++i)
#pragma unroll
        for (int hf = 0; hf < 2; ++hf) {
            int row = m0 + wm0 + i * 16 + rf + hf * 8;
            int pos = row & (L_ - 1);
#pragma unroll
            for (int j = 0; j < 8; ++j) {
                int col = n0 + wn0 + j * 8 + cf;
                float x0 = acc[i][j][hf * 2], x1 = acc[i][j][hf * 2 + 1];
                float y0, y1;
                if (MODE == 2) {
                    y0 = x0; y1 = x1;
                } else {
                    float4 tb = g_xt[(size_t)pos * 512 + (col >> 1)];
                    float c = (MODE == 0) ? tb.x : tb.z;
                    float s = (MODE == 0) ? tb.y : tb.w;
                    y0 = x0 * c - x1 * s;
                    y1 = x1 * c + x0 * s;
                }
                uint32_t h, l;
                split2(y0, y1, h, l);
                *reinterpret_cast<uint32_t*>(dh + (size_t)row * D_ + col) = h;
                *reinterpret_cast<uint32_t*>(dl + (size_t)row * D_ + col) = l;
            }
        }
}

// -------------------- A = (Q K^T) * decay, fp16 single -----------------------
__global__ __launch_bounds__(256) void qk_mm() {
    __shared__ __nv_bfloat16 sm[20480];
    __shared__ float pw[128], ipw[128];
    const int t = threadIdx.x;
    const int b = blockIdx.z;
    const int m0 = blockIdx.x << 7;  // keys
    const int n0 = blockIdx.y << 7;  // queries
    if (m0 > n0 || m0 + WIN < n0) return;  // causal + decay-truncated window

    if (t < 128) {
        pw[t] = exp2f((float)t * LOG2G);
        ipw[t] = exp2f(-(float)t * LOG2G);
    }

    float acc[2][8][4] = {};
    gemm_loop(acc,
              g_Qh + (size_t)(b * L_ + n0) * D_, g_Ql + (size_t)(b * L_ + n0) * D_,
              g_Kh + (size_t)(b * L_ + m0) * D_, g_Kl + (size_t)(b * L_ + m0) * D_,
              D_, D_, D_ / 32, sm, t);

    const int lane = t & 31, w = t >> 5;
    const int wm0 = (w >> 1) << 5, wn0 = (w & 1) << 6;
    const int rf = lane >> 2, cf = (lane & 3) << 1;
    const float base = exp2f((float)(n0 - m0) * LOG2G);
    __half* A = g_A + (size_t)b * L_ * L_;

#pragma unroll
    for (int i = 0; i < 2; ++i)
#pragma unroll
        for (int hf = 0; hf < 2; ++hf) {
            int r = wm0 + i * 16 + rf + hf * 8;
            int gn = n0 + r;
            float bp = base * pw[r];
#pragma unroll
            for (int j = 0; j < 8; ++j) {
                int c = wn0 + j * 8 + cf;
                int gm = m0 + c;
                float v0 = (gm <= gn) ? acc[i][j][hf * 2] * (bp * ipw[c]) : 0.f;
                float v1 = (gm + 1 <= gn) ? acc[i][j][hf * 2 + 1] * (bp * ipw[c + 1]) : 0.f;
                __half2 hv = __floats2half2_rn(v0, v1);
                *reinterpret_cast<__half2*>(A + (size_t)gn * L_ + gm) = hv;
            }
        }
}

// ------------------------------ out = A @ V ----------------------------------
__global__ __launch_bounds__(256) void av_mm(float* __restrict__ out) {
    __shared__ __half sm[15360];
    const int t = threadIdx.x;
    const int b = blockIdx.z;
    const int j0 = blockIdx.x << 7;  // output features
    const int n0 = blockIdx.y << 7;  // rows
    const int start = (n0 > WIN) ? (n0 - WIN) : 0;  // decay-truncated key start
    const int chunks = (n0 + 128 - start) >> 5;

    float acc[2][8][4] = {};
    gemm_loop_av(acc,
                 g_A + ((size_t)b * L_ + n0) * L_ + start,
                 g_Th + (size_t)b * L_ * D_ + (size_t)j0 * L_ + start,
                 g_Tl + (size_t)b * L_ * D_ + (size_t)j0 * L_ + start,
                 L_, L_, chunks, sm, t);

    const int lane = t & 31, w = t >> 5;
    const int wm0 = (w >> 1) << 5, wn0 = (w & 1) << 6;
    const int rf = lane >> 2, cf = (lane & 3) << 1;

#pragma unroll
    for (int i = 0; i < 2; ++i)
#pragma unroll
        for (int hf = 0; hf < 2; ++hf) {
            int row = n0 + wm0 + i * 16 + rf + hf * 8;
#pragma unroll
            for (int j = 0; j < 8; ++j) {
                int col = j0 + wn0 + j * 8 + cf;
                float2 v;
                v.x = acc[i][j][hf * 2];
                v.y = acc[i][j][hf * 2 + 1];
                *reinterpret_cast<float2*>(out + ((size_t)(b * L_ + row)) * D_ + col) = v;
            }
        }
}

// -----------------------------------------------------------------------------
extern "C" void kernel_launch(void* const* d_in, const int* in_sizes, int n_in,
                              void* d_out, int out_size) {
    const float* X = (const float*)d_in[0];
    const float* WQ = (const float*)d_in[1];
    const float* WK = (const float*)d_in[2];
    const float* WV = (const float*)d_in[3];
    float* out = (float*)d_out;

    cvt_x_kernel<<<(NBL * D_) / 1024, 256>>>(X);
    dim3 wg(32, 32);
    wt_kernel<0><<<wg, 256>>>(WQ);
    wt_kernel<1><<<wg, 256>>>(WK);
    wt_kernel<2><<<wg, 256>>>(WV);
    xt_kernel<<<(L_ * 512) / 256, 256>>>();

    proj_mm<0><<<dim3(8, 64), 256>>>();
    proj_mm<1><<<dim3(8, 64), 256>>>();
    proj_mm<2><<<dim3(8, 64), 256>>>();
    vt_kernel<<<dim3(64, 32, B_), 256>>>();

    qk_mm<<<dim3(16, 16, B_), 256>>>();
    av_mm<<<dim3(8, 16, B_), 256>>>(out);
}

// round 7
// speedup vs baseline: 2.8571x; 2.0724x over previous
#include <cuda_runtime.h>
#include <cuda_fp16.h>
#include <stdint.h>
#include <math.h>

#define B_ 4
#define L_ 2048
#define D_ 1024
#define NBL (B_ * L_)
#define WIN 512                         // decay truncation window (γ^512 ≈ 1e-7)

#define LOG2G  (-0.045803734f)          // log2(0.96875)
#define L2_1E4 (13.287712379549449f)    // log2(10000)

// ------------------- global scratch (allocation-free rule) -------------------
__device__ __align__(16) __half g_X16[NBL * D_];
__device__ __align__(16) __half g_W16[3][D_ * D_];        // transposed [n][k]
__device__ __align__(16) __half g_Q16[NBL * D_];
__device__ __align__(16) __half g_K16[NBL * D_];
__device__ __align__(16) __half g_V16[NBL * D_];
__device__ __align__(16) __half g_T16[NBL * D_];          // V^T [d][l]
__device__ __align__(16) __half g_A[(size_t)B_ * L_ * L_];
__device__ __align__(16) float4 g_xt[(size_t)L_ * (D_ / 2)];  // cQ,sQ,cK,sK

// ------------------------------- helpers -------------------------------------
__device__ __forceinline__ uint32_t smem_u32(const void* p) {
    uint32_t a;
    asm("{ .reg .u64 t; cvta.to.shared.u64 t, %1; cvt.u32.u64 %0, t; }"
        : "=r"(a) : "l"(p));
    return a;
}

__device__ __forceinline__ void ldm4(uint32_t* r, uint32_t a) {
    asm volatile("ldmatrix.sync.aligned.m8n8.x4.shared.b16 {%0,%1,%2,%3}, [%4];"
                 : "=r"(r[0]), "=r"(r[1]), "=r"(r[2]), "=r"(r[3]) : "r"(a));
}

__device__ __forceinline__ void mma_f16(float* c, const uint32_t* a, const uint32_t* b) {
    asm volatile(
        "mma.sync.aligned.m16n8k16.row.col.f32.f16.f16.f32 "
        "{%0,%1,%2,%3}, {%4,%5,%6,%7}, {%8,%9}, {%0,%1,%2,%3};"
        : "+f"(c[0]), "+f"(c[1]), "+f"(c[2]), "+f"(c[3])
        : "r"(a[0]), "r"(a[1]), "r"(a[2]), "r"(a[3]), "r"(b[0]), "r"(b[1]));
}

// copy 128 rows x 32 cols (16-bit elems), gmem(stride ld) -> smem(stride 40)
__device__ __forceinline__ void ldtile(uint16_t* s, const uint16_t* __restrict__ g,
                                       int ld, int t) {
#pragma unroll
    for (int it = 0; it < 2; ++it) {
        int idx = t + it * 256;
        int r = idx >> 2, sg = (idx & 3) << 3;
        *reinterpret_cast<float4*>(s + r * 40 + sg) =
            *reinterpret_cast<const float4*>(g + (size_t)r * ld + sg);
    }
}

// ---------------- CTA 128x128 GEMM mainloop: single fp16 x fp16 --------------
// acc per warp: [m 0..1][n 0..7][c0..3]
__device__ __forceinline__ void gemm_loop1(
    float acc[2][8][4],
    const __half* __restrict__ Ag, const __half* __restrict__ Bg,
    int lda, int ldb, int nchunks, uint16_t* sm, int t) {
    uint16_t* sA = sm;            // 128 x 40 halves
    uint16_t* sB = sm + 5120;

    const int lane = t & 31, w = t >> 5;
    const int wm0 = (w >> 1) << 5;   // warp m offset (0,32,64,96)
    const int wn0 = (w & 1) << 6;    // warp n offset (0,64)

    const int arow = wm0 + (lane & 15);
    const int acol = (lane >> 4) << 3;
    const uint32_t aA = smem_u32(sA) + (uint32_t)(arow * 40 + acol) * 2;
    const int brow = wn0 + ((lane >> 4) << 3) + (lane & 7);
    const int bcol = ((lane >> 3) & 1) << 3;
    const uint32_t bB = smem_u32(sB) + (uint32_t)(brow * 40 + bcol) * 2;

    for (int ch = 0; ch < nchunks; ++ch) {
        const int k0 = ch * 32;
        ldtile(sA, (const uint16_t*)Ag + k0, lda, t);
        ldtile(sB, (const uint16_t*)Bg + k0, ldb, t);
        __syncthreads();

#pragma unroll
        for (int kk = 0; kk < 2; ++kk) {
            const uint32_t kb = kk * 32;  // 16 halves = 32 bytes
            uint32_t af[2][4], bf[8][2];
#pragma unroll
            for (int i = 0; i < 2; ++i)
                ldm4(af[i], aA + i * 16 * 80 + kb);
#pragma unroll
            for (int jp = 0; jp < 4; ++jp) {
                uint32_t tp[4];
                ldm4(tp, bB + jp * 16 * 80 + kb);
                bf[2 * jp][0] = tp[0];     bf[2 * jp][1] = tp[1];
                bf[2 * jp + 1][0] = tp[2]; bf[2 * jp + 1][1] = tp[3];
            }
#pragma unroll
            for (int i = 0; i < 2; ++i)
#pragma unroll
                for (int j = 0; j < 8; ++j)
                    mma_f16(acc[i][j], af[i], bf[j]);
        }
        __syncthreads();
    }
}

// ------------------------------- prep kernels --------------------------------
__global__ __launch_bounds__(256) void cvt_x_kernel(const float* __restrict__ X) {
    size_t i = ((size_t)blockIdx.x * 256 + threadIdx.x) * 4;
    float4 v = *reinterpret_cast<const float4*>(X + i);
    __half2 a = __floats2half2_rn(v.x, v.y);
    __half2 b = __floats2half2_rn(v.z, v.w);
    uint2 o;
    o.x = *reinterpret_cast<uint32_t*>(&a);
    o.y = *reinterpret_cast<uint32_t*>(&b);
    *reinterpret_cast<uint2*>(g_X16 + i) = o;
}

// transpose W[k][n] -> Wt[n][k] fp16
template <int S>
__global__ __launch_bounds__(256) void wt_kernel(const float* __restrict__ W) {
    __shared__ float ts[32][33];
    int n0 = blockIdx.x * 32, k0 = blockIdx.y * 32;
    int tx = threadIdx.x & 31, ty = threadIdx.x >> 5;
#pragma unroll
    for (int j = 0; j < 4; ++j)
        ts[ty + 8 * j][tx] = W[(size_t)(k0 + ty + 8 * j) * D_ + n0 + tx];
    __syncthreads();
#pragma unroll
    for (int j = 0; j < 4; ++j)
        g_W16[S][(size_t)(n0 + ty + 8 * j) * D_ + k0 + tx] =
            __float2half_rn(ts[tx][ty + 8 * j]);
}

// transpose V[l][d] -> Vt[d][l] fp16
__global__ __launch_bounds__(256) void vt_kernel() {
    __shared__ __half ts[32][34];
    int b = blockIdx.z;
    int l0 = blockIdx.x * 32, d0 = blockIdx.y * 32;
    int tx = threadIdx.x & 31, ty = threadIdx.x >> 5;
    const __half* v = g_V16 + (size_t)b * L_ * D_;
    __half* d = g_T16 + (size_t)b * L_ * D_;
#pragma unroll
    for (int j = 0; j < 4; ++j)
        ts[ty + 8 * j][tx] = v[(size_t)(l0 + ty + 8 * j) * D_ + d0 + tx];
    __syncthreads();
#pragma unroll
    for (int j = 0; j < 4; ++j)
        d[(size_t)(d0 + ty + 8 * j) * L_ + l0 + tx] = ts[tx][ty + 8 * j];
}

// precompute xPos rotation table
__global__ __launch_bounds__(256) void xt_kernel() {
    int idx = blockIdx.x * 256 + threadIdx.x;  // pos*512 + cp
    int pos = idx >> 9;
    int cp = idx & 511;
    float sv = (2.0f * cp + 409.6f) * (1.0f / 1433.6f);
    float sc = exp2f((float)pos * (1.0f / 512.0f) * log2f(sv));
    float invf = exp2f(-(float)cp * (L2_1E4 / 512.0f));
    float s, c;
    sincosf((float)pos * invf, &s, &c);
    g_xt[idx] = make_float4(c * sc, s * sc, c / sc, s / sc);
}

// ----------------------- projection GEMMs (Q / K / V) ------------------------
template <int MODE>  // 0=Q, 1=K, 2=V
__global__ __launch_bounds__(256) void proj_mm() {
    __shared__ uint16_t sm[10240];
    float acc[2][8][4] = {};
    const int t = threadIdx.x;
    const int n0 = blockIdx.x << 7, m0 = blockIdx.y << 7;

    gemm_loop1(acc,
               g_X16 + (size_t)m0 * D_,
               g_W16[MODE] + (size_t)n0 * D_,
               D_, D_, D_ / 32, sm, t);

    const int lane = t & 31, w = t >> 5;
    const int wm0 = (w >> 1) << 5, wn0 = (w & 1) << 6;
    const int rf = lane >> 2, cf = (lane & 3) << 1;
    __half* dst = (MODE == 0) ? g_Q16 : (MODE == 1 ? g_K16 : g_V16);

#pragma unroll
    for (int i = 0; i < 2; ++i)
#pragma unroll
        for (int hf = 0; hf < 2; ++hf) {
            int row = m0 + wm0 + i * 16 + rf + hf * 8;
            int pos = row & (L_ - 1);
#pragma unroll
            for (int j = 0; j < 8; ++j) {
                int col = n0 + wn0 + j * 8 + cf;
                float x0 = acc[i][j][hf * 2], x1 = acc[i][j][hf * 2 + 1];
                float y0, y1;
                if (MODE == 2) {
                    y0 = x0; y1 = x1;
                } else {
                    float4 tb = g_xt[(size_t)pos * 512 + (col >> 1)];
                    float c = (MODE == 0) ? tb.x : tb.z;
                    float s = (MODE == 0) ? tb.y : tb.w;
                    y0 = x0 * c - x1 * s;
                    y1 = x1 * c + x0 * s;
                }
                __half2 hv = __floats2half2_rn(y0, y1);
                *reinterpret_cast<__half2*>(dst + (size_t)row * D_ + col) = hv;
            }
        }
}

// -------------------- A = (Q K^T) * decay, fp16 ------------------------------
__global__ __launch_bounds__(256) void qk_mm() {
    __shared__ uint16_t sm[10240];
    __shared__ float pw[128], ipw[128];
    const int t = threadIdx.x;
    const int b = blockIdx.z;
    const int m0 = blockIdx.x << 7;  // keys
    const int n0 = blockIdx.y << 7;  // queries
    if (m0 > n0 || m0 + WIN < n0) return;  // causal + decay-truncated window

    if (t < 128) {
        pw[t] = exp2f((float)t * LOG2G);
        ipw[t] = exp2f(-(float)t * LOG2G);
    }

    float acc[2][8][4] = {};
    gemm_loop1(acc,
               g_Q16 + (size_t)(b * L_ + n0) * D_,
               g_K16 + (size_t)(b * L_ + m0) * D_,
               D_, D_, D_ / 32, sm, t);

    const int lane = t & 31, w = t >> 5;
    const int wm0 = (w >> 1) << 5, wn0 = (w & 1) << 6;
    const int rf = lane >> 2, cf = (lane & 3) << 1;
    const float base = exp2f((float)(n0 - m0) * LOG2G);
    __half* A = g_A + (size_t)b * L_ * L_;

#pragma unroll
    for (int i = 0; i < 2; ++i)
#pragma unroll
        for (int hf = 0; hf < 2; ++hf) {
            int r = wm0 + i * 16 + rf + hf * 8;
            int gn = n0 + r;
            float bp = base * pw[r];
#pragma unroll
            for (int j = 0; j < 8; ++j) {
                int c = wn0 + j * 8 + cf;
                int gm = m0 + c;
                float v0 = (gm <= gn) ? acc[i][j][hf * 2] * (bp * ipw[c]) : 0.f;
                float v1 = (gm + 1 <= gn) ? acc[i][j][hf * 2 + 1] * (bp * ipw[c + 1]) : 0.f;
                __half2 hv = __floats2half2_rn(v0, v1);
                *reinterpret_cast<__half2*>(A + (size_t)gn * L_ + gm) = hv;
            }
        }
}

// ------------------------------ out = A @ V ----------------------------------
__global__ __launch_bounds__(256) void av_mm(float* __restrict__ out) {
    __shared__ uint16_t sm[10240];
    const int t = threadIdx.x;
    const int b = blockIdx.z;
    const int j0 = blockIdx.x << 7;  // output features
    const int n0 = blockIdx.y << 7;  // rows
    const int start = (n0 > WIN) ? (n0 - WIN) : 0;  // decay-truncated key start
    const int chunks = (n0 + 128 - start) >> 5;

    float acc[2][8][4] = {};
    gemm_loop1(acc,
               g_A + ((size_t)b * L_ + n0) * L_ + start,
               g_T16 + (size_t)b * L_ * D_ + (size_t)j0 * L_ + start,
               L_, L_, chunks, sm, t);

    const int lane = t & 31, w = t >> 5;
    const int wm0 = (w >> 1) << 5, wn0 = (w & 1) << 6;
    const int rf = lane >> 2, cf = (lane & 3) << 1;

#pragma unroll
    for (int i = 0; i < 2; ++i)
#pragma unroll
        for (int hf = 0; hf < 2; ++hf) {
            int row = n0 + wm0 + i * 16 + rf + hf * 8;
#pragma unroll
            for (int j = 0; j < 8; ++j) {
                int col = j0 + wn0 + j * 8 + cf;
                float2 v;
                v.x = acc[i][j][hf * 2];
                v.y = acc[i][j][hf * 2 + 1];
                *reinterpret_cast<float2*>(out + ((size_t)(b * L_ + row)) * D_ + col) = v;
            }
        }
}

// -----------------------------------------------------------------------------
extern "C" void kernel_launch(void* const* d_in, const int* in_sizes, int n_in,
                              void* d_out, int out_size) {
    const float* X = (const float*)d_in[0];
    const float* WQ = (const float*)d_in[1];
    const float* WK = (const float*)d_in[2];
    const float* WV = (const float*)d_in[3];
    float* out = (float*)d_out;

    cvt_x_kernel<<<(NBL * D_) / 1024, 256>>>(X);
    dim3 wg(32, 32);
    wt_kernel<0><<<wg, 256>>>(WQ);
    wt_kernel<1><<<wg, 256>>>(WK);
    wt_kernel<2><<<wg, 256>>>(WV);
    xt_kernel<<<(L_ * 512) / 256, 256>>>();

    proj_mm<0><<<dim3(8, 64), 256>>>();
    proj_mm<1><<<dim3(8, 64), 256>>>();
    proj_mm<2><<<dim3(8, 64), 256>>>();
    vt_kernel<<<dim3(64, 32, B_), 256>>>();

    qk_mm<<<dim3(16, 16, B_), 256>>>();
    av_mm<<<dim3(8, 16, B_), 256>>>(out);
}

// round 9
// speedup vs baseline: 3.8301x; 1.3405x over previous
#include <cuda_runtime.h>
#include <cuda_fp16.h>
#include <stdint.h>
#include <math.h>

#define B_ 4
#define L_ 2048
#define D_ 1024
#define NBL (B_ * L_)
#define WIN 512                         // decay truncation window (γ^512 ≈ 9e-8)

#define LOG2G  (-0.045803734f)          // log2(0.96875)
#define L2_1E4 (13.287712379549449f)    // log2(10000)

// ------------------- global scratch (allocation-free rule) -------------------
__device__ __align__(16) __half g_X16[NBL * D_];
__device__ __align__(16) __half g_W16[3][D_ * D_];        // transposed [n][k]
__device__ __align__(16) __half g_Q16[NBL * D_];
__device__ __align__(16) __half g_K16[NBL * D_];
__device__ __align__(16) __half g_T16[NBL * D_];          // V^T [d][l]
__device__ __align__(16) __half g_A[(size_t)B_ * L_ * L_];
__device__ __align__(16) float4 g_xt[(size_t)L_ * (D_ / 2)];  // cQ,sQ,cK,sK

// ------------------------------- helpers -------------------------------------
__device__ __forceinline__ uint32_t smem_u32(const void* p) {
    uint32_t a;
    asm("{ .reg .u64 t; cvta.to.shared.u64 t, %1; cvt.u32.u64 %0, t; }"
        : "=r"(a) : "l"(p));
    return a;
}

__device__ __forceinline__ void ldm4(uint32_t* r, uint32_t a) {
    asm volatile("ldmatrix.sync.aligned.m8n8.x4.shared.b16 {%0,%1,%2,%3}, [%4];"
                 : "=r"(r[0]), "=r"(r[1]), "=r"(r[2]), "=r"(r[3]) : "r"(a));
}

__device__ __forceinline__ void mma_f16(float* c, const uint32_t* a, const uint32_t* b) {
    asm volatile(
        "mma.sync.aligned.m16n8k16.row.col.f32.f16.f16.f32 "
        "{%0,%1,%2,%3}, {%4,%5,%6,%7}, {%8,%9}, {%0,%1,%2,%3};"
        : "+f"(c[0]), "+f"(c[1]), "+f"(c[2]), "+f"(c[3])
        : "r"(a[0]), "r"(a[1]), "r"(a[2]), "r"(a[3]), "r"(b[0]), "r"(b[1]));
}

// copy 128 rows x 64 cols (16-bit elems), gmem(stride ld) -> smem(stride 72)
__device__ __forceinline__ void ldtile64(uint16_t* s, const uint16_t* __restrict__ g,
                                         int ld, int t) {
#pragma unroll
    for (int it = 0; it < 4; ++it) {
        int idx = t + it * 256;
        int r = idx >> 3, sg = (idx & 7) << 3;
        *reinterpret_cast<float4*>(s + r * 72 + sg) =
            *reinterpret_cast<const float4*>(g + (size_t)r * ld + sg);
    }
}

// ---------------- CTA 128x128 GEMM mainloop: fp16, K-chunk 64 ----------------
// acc per warp: [m 0..1][n 0..7][c0..3]
__device__ __forceinline__ void gemm_loop1(
    float acc[2][8][4],
    const __half* __restrict__ Ag, const __half* __restrict__ Bg,
    int lda, int ldb, int nch64, uint16_t* sm, int t) {
    uint16_t* sA = sm;            // 128 x 72 halves
    uint16_t* sB = sm + 9216;

    const int lane = t & 31, w = t >> 5;
    const int wm0 = (w >> 1) << 5;   // warp m offset (0,32,64,96)
    const int wn0 = (w & 1) << 6;    // warp n offset (0,64)

    const int arow = wm0 + (lane & 15);
    const int acol = (lane >> 4) << 3;
    const uint32_t aA = smem_u32(sA) + (uint32_t)(arow * 72 + acol) * 2;
    const int brow = wn0 + ((lane >> 4) << 3) + (lane & 7);
    const int bcol = ((lane >> 3) & 1) << 3;
    const uint32_t bB = smem_u32(sB) + (uint32_t)(brow * 72 + bcol) * 2;

    for (int ch = 0; ch < nch64; ++ch) {
        const int k0 = ch * 64;
        ldtile64(sA, (const uint16_t*)Ag + k0, lda, t);
        ldtile64(sB, (const uint16_t*)Bg + k0, ldb, t);
        __syncthreads();

#pragma unroll
        for (int kk = 0; kk < 4; ++kk) {
            const uint32_t kb = kk * 32;  // 16 halves = 32 bytes
            uint32_t af[2][4], bf[8][2];
#pragma unroll
            for (int i = 0; i < 2; ++i)
                ldm4(af[i], aA + i * 16 * 144 + kb);
#pragma unroll
            for (int jp = 0; jp < 4; ++jp) {
                uint32_t tp[4];
                ldm4(tp, bB + jp * 16 * 144 + kb);
                bf[2 * jp][0] = tp[0];     bf[2 * jp][1] = tp[1];
                bf[2 * jp + 1][0] = tp[2]; bf[2 * jp + 1][1] = tp[3];
            }
#pragma unroll
            for (int i = 0; i < 2; ++i)
#pragma unroll
                for (int j = 0; j < 8; ++j)
                    mma_f16(acc[i][j], af[i], bf[j]);
        }
        __syncthreads();
    }
}

// --------------------------- fused prep: cvt X + xt table --------------------
__global__ __launch_bounds__(256) void prep_kernel(const float* __restrict__ X) {
    int bx = blockIdx.x;
    if (bx < (NBL * D_) / 1024) {
        size_t i = ((size_t)bx * 256 + threadIdx.x) * 4;
        float4 v = *reinterpret_cast<const float4*>(X + i);
        __half2 a = __floats2half2_rn(v.x, v.y);
        __half2 b = __floats2half2_rn(v.z, v.w);
        uint2 o;
        o.x = *reinterpret_cast<uint32_t*>(&a);
        o.y = *reinterpret_cast<uint32_t*>(&b);
        *reinterpret_cast<uint2*>(g_X16 + i) = o;
    } else {
        int idx = (bx - (NBL * D_) / 1024) * 256 + threadIdx.x;  // pos*512 + cp
        int pos = idx >> 9;
        int cp = idx & 511;
        float sv = (2.0f * cp + 409.6f) * (1.0f / 1433.6f);
        float sc = exp2f((float)pos * (1.0f / 512.0f) * log2f(sv));
        float invf = exp2f(-(float)cp * (L2_1E4 / 512.0f));
        float s, c;
        sincosf((float)pos * invf, &s, &c);
        g_xt[idx] = make_float4(c * sc, s * sc, c / sc, s / sc);
    }
}

// transpose W[k][n] -> Wt[n][k] fp16, all three weights (z selects)
__global__ __launch_bounds__(256) void wt_kernel(const float* __restrict__ WQ,
                                                 const float* __restrict__ WK,
                                                 const float* __restrict__ WV) {
    __shared__ float ts[32][33];
    const int S = blockIdx.z;
    const float* W = (S == 0) ? WQ : (S == 1 ? WK : WV);
    int n0 = blockIdx.x * 32, k0 = blockIdx.y * 32;
    int tx = threadIdx.x & 31, ty = threadIdx.x >> 5;
#pragma unroll
    for (int j = 0; j < 4; ++j)
        ts[ty + 8 * j][tx] = W[(size_t)(k0 + ty + 8 * j) * D_ + n0 + tx];
    __syncthreads();
#pragma unroll
    for (int j = 0; j < 4; ++j)
        g_W16[S][(size_t)(n0 + ty + 8 * j) * D_ + k0 + tx] =
            __float2half_rn(ts[tx][ty + 8 * j]);
}

// --------------- fused projection GEMM: z = 0:Q, 1:K, 2:V(->V^T) -------------
__global__ __launch_bounds__(256) void proj_mm() {
    __shared__ uint16_t sm[18432];   // 36 KB: gemm tiles, then V-transpose staging
    float acc[2][8][4] = {};
    const int t = threadIdx.x;
    const int MODE = blockIdx.z;
    const int n0 = blockIdx.x << 7, m0 = blockIdx.y << 7;

    gemm_loop1(acc,
               g_X16 + (size_t)m0 * D_,
               g_W16[MODE] + (size_t)n0 * D_,
               D_, D_, D_ / 64, sm, t);

    const int lane = t & 31, w = t >> 5;
    const int wm0 = (w >> 1) << 5, wn0 = (w & 1) << 6;
    const int rf = lane >> 2, cf = (lane & 3) << 1;

    if (MODE == 2) {
        // ---- V: write transposed directly to g_T16[d][l] via smem staging ----
#pragma unroll
        for (int i = 0; i < 2; ++i)
#pragma unroll
            for (int hf = 0; hf < 2; ++hf) {
                int r = wm0 + i * 16 + rf + hf * 8;
#pragma unroll
                for (int j = 0; j < 8; ++j) {
                    int c = wn0 + j * 8 + cf;
                    sm[(uint32_t)c * 136 + r] =
                        (uint16_t)__half_as_ushort(__float2half_rn(acc[i][j][hf * 2]));
                    sm[(uint32_t)(c + 1) * 136 + r] =
                        (uint16_t)__half_as_ushort(__float2half_rn(acc[i][j][hf * 2 + 1]));
                }
            }
        __syncthreads();
        const int b = m0 >> 11;
        const int l0 = m0 & (L_ - 1);
        __half* T = g_T16 + (size_t)b * L_ * D_;
#pragma unroll
        for (int it = 0; it < 8; ++it) {
            int idx = t + it * 256;
            int c = idx >> 4;                 // local feature 0..127
            int sg = (idx & 15) << 3;         // local row segment
            float4 v = *reinterpret_cast<const float4*>(sm + (uint32_t)c * 136 + sg);
            *reinterpret_cast<float4*>(T + (size_t)(n0 + c) * L_ + l0 + sg) = v;
        }
        return;
    }

    // ---- Q / K: xPos rotation epilogue ----
    __half* dst = (MODE == 0) ? g_Q16 : g_K16;
#pragma unroll
    for (int i = 0; i < 2; ++i)
#pragma unroll
        for (int hf = 0; hf < 2; ++hf) {
            int row = m0 + wm0 + i * 16 + rf + hf * 8;
            int pos = row & (L_ - 1);
#pragma unroll
            for (int j = 0; j < 8; ++j) {
                int col = n0 + wn0 + j * 8 + cf;
                float x0 = acc[i][j][hf * 2], x1 = acc[i][j][hf * 2 + 1];
                float4 tb = g_xt[(size_t)pos * 512 + (col >> 1)];
                float c = (MODE == 0) ? tb.x : tb.z;
                float s = (MODE == 0) ? tb.y : tb.w;
                float y0 = x0 * c - x1 * s;
                float y1 = x1 * c + x0 * s;
                __half2 hv = __floats2half2_rn(y0, y1);
                *reinterpret_cast<__half2*>(dst + (size_t)row * D_ + col) = hv;
            }
        }
}

// -------------------- A = (Q K^T) * decay, fp16 (window tiles only) ----------
__global__ __launch_bounds__(256) void qk_mm() {
    __shared__ uint16_t sm[18432];
    __shared__ float pw[128], ipw[128];
    const int t = threadIdx.x;
    const int b = blockIdx.z;
    const int nt = blockIdx.y;                 // query tile
    const int mt = nt - 4 + (int)blockIdx.x;   // key tile within window
    if (mt < 0) return;
    const int n0 = nt << 7, m0 = mt << 7;

    if (t < 128) {
        pw[t] = exp2f((float)t * LOG2G);
        ipw[t] = exp2f(-(float)t * LOG2G);
    }

    float acc[2][8][4] = {};
    gemm_loop1(acc,
               g_Q16 + (size_t)(b * L_ + n0) * D_,
               g_K16 + (size_t)(b * L_ + m0) * D_,
               D_, D_, D_ / 64, sm, t);

    const int lane = t & 31, w = t >> 5;
    const int wm0 = (w >> 1) << 5, wn0 = (w & 1) << 6;
    const int rf = lane >> 2, cf = (lane & 3) << 1;
    const float base = exp2f((float)(n0 - m0) * LOG2G);
    __half* A = g_A + (size_t)b * L_ * L_;

#pragma unroll
    for (int i = 0; i < 2; ++i)
#pragma unroll
        for (int hf = 0; hf < 2; ++hf) {
            int r = wm0 + i * 16 + rf + hf * 8;
            int gn = n0 + r;
            float bp = base * pw[r];
#pragma unroll
            for (int j = 0; j < 8; ++j) {
                int c = wn0 + j * 8 + cf;
                int gm = m0 + c;
                float v0 = (gm <= gn) ? acc[i][j][hf * 2] * (bp * ipw[c]) : 0.f;
                float v1 = (gm + 1 <= gn) ? acc[i][j][hf * 2 + 1] * (bp * ipw[c + 1]) : 0.f;
                __half2 hv = __floats2half2_rn(v0, v1);
                *reinterpret_cast<__half2*>(A + (size_t)gn * L_ + gm) = hv;
            }
        }
}

// ------------------------------ out = A @ V ----------------------------------
__global__ __launch_bounds__(256) void av_mm(float* __restrict__ out) {
    __shared__ uint16_t sm[18432];
    const int t = threadIdx.x;
    const int b = blockIdx.z;
    const int j0 = blockIdx.x << 7;                     // output features
    const int n0 = ((int)gridDim.y - 1 - (int)blockIdx.y) << 7;  // heavy tiles first
    const int start = (n0 > WIN) ? (n0 - WIN) : 0;      // decay-truncated key start
    const int nch = (n0 + 128 - start) >> 6;

    float acc[2][8][4] = {};
    gemm_loop1(acc,
               g_A + ((size_t)b * L_ + n0) * L_ + start,
               g_T16 + (size_t)b * L_ * D_ + (size_t)j0 * L_ + start,
               L_, L_, nch, sm, t);

    const int lane = t & 31, w = t >> 5;
    const int wm0 = (w >> 1) << 5, wn0 = (w & 1) << 6;
    const int rf = lane >> 2, cf = (lane & 3) << 1;

#pragma unroll
    for (int i = 0; i < 2; ++i)
#pragma unroll
        for (int hf = 0; hf < 2; ++hf) {
            int row = n0 + wm0 + i * 16 + rf + hf * 8;
#pragma unroll
            for (int j = 0; j < 8; ++j) {
                int col = j0 + wn0 + j * 8 + cf;
                float2 v;
                v.x = acc[i][j][hf * 2];
                v.y = acc[i][j][hf * 2 + 1];
                *reinterpret_cast<float2*>(out + ((size_t)(b * L_ + row)) * D_ + col) = v;
            }
        }
}

// -----------------------------------------------------------------------------
extern "C" void kernel_launch(void* const* d_in, const int* in_sizes, int n_in,
                              void* d_out, int out_size) {
    const float* X = (const float*)d_in[0];
    const float* WQ = (const float*)d_in[1];
    const float* WK = (const float*)d_in[2];
    const float* WV = (const float*)d_in[3];
    float* out = (float*)d_out;

    prep_kernel<<<(NBL * D_) / 1024 + (L_ * 512) / 256, 256>>>(X);
    wt_kernel<<<dim3(32, 32, 3), 256>>>(WQ, WK, WV);
    proj_mm<<<dim3(8, 64, 3), 256>>>();
    qk_mm<<<dim3(5, 16, B_), 256>>>();
    av_mm<<<dim3(8, 16, B_), 256>>>(out);
}

// round 10
// speedup vs baseline: 4.2142x; 1.1003x over previous
#include <cuda_runtime.h>
#include <cuda_fp16.h>
#include <stdint.h>
#include <math.h>

#define B_ 4
#define L_ 2048
#define D_ 1024
#define NBL (B_ * L_)
#define WIN 512                         // decay truncation window (γ^512 ≈ 9e-8)

#define LOG2G  (-0.045803734f)          // log2(0.96875)
#define L2_1E4 (13.287712379549449f)    // log2(10000)

#define STG_BYTES 36864                 // one stage: A(18432) + B(18432)
#define GEMM_SMEM (2 * STG_BYTES)       // 72 KB, 2-stage

// ------------------- global scratch (allocation-free rule) -------------------
__device__ __align__(16) __half g_X16[NBL * D_];
__device__ __align__(16) __half g_W16[3][D_ * D_];        // transposed [n][k]
__device__ __align__(16) __half g_Q16[NBL * D_];
__device__ __align__(16) __half g_K16[NBL * D_];
__device__ __align__(16) __half g_T16[NBL * D_];          // V^T [d][l]
__device__ __align__(16) __half g_A[(size_t)B_ * L_ * L_];
__device__ __align__(16) float4 g_xt[(size_t)L_ * (D_ / 2)];  // cQ,sQ,cK,sK

// ------------------------------- helpers -------------------------------------
__device__ __forceinline__ uint32_t smem_u32(const void* p) {
    uint32_t a;
    asm("{ .reg .u64 t; cvta.to.shared.u64 t, %1; cvt.u32.u64 %0, t; }"
        : "=r"(a) : "l"(p));
    return a;
}

__device__ __forceinline__ void ldm4(uint32_t* r, uint32_t a) {
    asm volatile("ldmatrix.sync.aligned.m8n8.x4.shared.b16 {%0,%1,%2,%3}, [%4];"
                 : "=r"(r[0]), "=r"(r[1]), "=r"(r[2]), "=r"(r[3]) : "r"(a));
}

__device__ __forceinline__ void mma_f16(float* c, const uint32_t* a, const uint32_t* b) {
    asm volatile(
        "mma.sync.aligned.m16n8k16.row.col.f32.f16.f16.f32 "
        "{%0,%1,%2,%3}, {%4,%5,%6,%7}, {%8,%9}, {%0,%1,%2,%3};"
        : "+f"(c[0]), "+f"(c[1]), "+f"(c[2]), "+f"(c[3])
        : "r"(a[0]), "r"(a[1]), "r"(a[2]), "r"(a[3]), "r"(b[0]), "r"(b[1]));
}

__device__ __forceinline__ void cp16(uint32_t dst, const void* src) {
    asm volatile("cp.async.cg.shared.global [%0], [%1], 16;" :: "r"(dst), "l"(src));
}
__device__ __forceinline__ void cp_commit() {
    asm volatile("cp.async.commit_group;" ::: "memory");
}
template <int N>
__device__ __forceinline__ void cp_wait() {
    asm volatile("cp.async.wait_group %0;" :: "n"(N) : "memory");
}

// async-copy 128 rows x 64 cols (16-bit), gmem(stride ld) -> smem(stride 72)
__device__ __forceinline__ void cpa64(uint32_t sb, const uint16_t* __restrict__ g,
                                      int ld, int t) {
#pragma unroll
    for (int it = 0; it < 4; ++it) {
        int idx = t + it * 256;
        int r = idx >> 3, sg = (idx & 7) << 3;
        cp16(sb + (uint32_t)(r * 72 + sg) * 2, g + (size_t)r * ld + sg);
    }
}

// issue one chunk (A tile + B tile) into a stage
__device__ __forceinline__ void issue_chunk(uint32_t stage,
                                            const uint16_t* __restrict__ Ag,
                                            const uint16_t* __restrict__ Bg,
                                            int lda, int ldb, int k0, int t) {
    cpa64(stage, Ag + k0, lda, t);
    cpa64(stage + 18432, Bg + k0, ldb, t);
    cp_commit();
}

// -------- CTA 128x128 GEMM mainloop: fp16, K-chunk 64, 2-stage cp.async ------
// acc per warp: [m 0..1][n 0..7][c0..3]
__device__ __forceinline__ void gemm_loop1(
    float acc[2][8][4],
    const __half* __restrict__ Ag, const __half* __restrict__ Bg,
    int lda, int ldb, int nch64, uint32_t smb, int t) {
    const int lane = t & 31, w = t >> 5;
    const int wm0 = (w >> 1) << 5;   // warp m offset (0,32,64,96)
    const int wn0 = (w & 1) << 6;    // warp n offset (0,64)

    const int arow = wm0 + (lane & 15);
    const int acol = (lane >> 4) << 3;
    const uint32_t aOff = (uint32_t)(arow * 72 + acol) * 2;
    const int brow = wn0 + ((lane >> 4) << 3) + (lane & 7);
    const int bcol = ((lane >> 3) & 1) << 3;
    const uint32_t bOff = 18432u + (uint32_t)(brow * 72 + bcol) * 2;

    const uint16_t* Au = (const uint16_t*)Ag;
    const uint16_t* Bu = (const uint16_t*)Bg;

    issue_chunk(smb, Au, Bu, lda, ldb, 0, t);

    for (int ch = 0; ch < nch64; ++ch) {
        if (ch + 1 < nch64) {
            issue_chunk(smb + ((ch + 1) & 1) * STG_BYTES, Au, Bu, lda, ldb,
                        (ch + 1) * 64, t);
            cp_wait<1>();
        } else {
            cp_wait<0>();
        }
        __syncthreads();

        const uint32_t sb = smb + (ch & 1) * STG_BYTES;
        const uint32_t aA = sb + aOff;
        const uint32_t bB = sb + bOff;

#pragma unroll
        for (int kk = 0; kk < 4; ++kk) {
            const uint32_t kb = kk * 32;  // 16 halves = 32 bytes
            uint32_t af[2][4], bf[8][2];
#pragma unroll
            for (int i = 0; i < 2; ++i)
                ldm4(af[i], aA + i * 16 * 144 + kb);
#pragma unroll
            for (int jp = 0; jp < 4; ++jp) {
                uint32_t tp[4];
                ldm4(tp, bB + jp * 16 * 144 + kb);
                bf[2 * jp][0] = tp[0];     bf[2 * jp][1] = tp[1];
                bf[2 * jp + 1][0] = tp[2]; bf[2 * jp + 1][1] = tp[3];
            }
#pragma unroll
            for (int i = 0; i < 2; ++i)
#pragma unroll
                for (int j = 0; j < 8; ++j)
                    mma_f16(acc[i][j], af[i], bf[j]);
        }
        __syncthreads();   // stage (ch&1) free for reuse at iteration ch+1's issue
    }
}

// --------------------------- fused prep: cvt X + xt table --------------------
__global__ __launch_bounds__(256) void prep_kernel(const float* __restrict__ X) {
    int bx = blockIdx.x;
    if (bx < (NBL * D_) / 1024) {
        size_t i = ((size_t)bx * 256 + threadIdx.x) * 4;
        float4 v = *reinterpret_cast<const float4*>(X + i);
        __half2 a = __floats2half2_rn(v.x, v.y);
        __half2 b = __floats2half2_rn(v.z, v.w);
        uint2 o;
        o.x = *reinterpret_cast<uint32_t*>(&a);
        o.y = *reinterpret_cast<uint32_t*>(&b);
        *reinterpret_cast<uint2*>(g_X16 + i) = o;
    } else {
        int idx = (bx - (NBL * D_) / 1024) * 256 + threadIdx.x;  // pos*512 + cp
        int pos = idx >> 9;
        int cp = idx & 511;
        float sv = (2.0f * cp + 409.6f) * (1.0f / 1433.6f);
        float sc = exp2f((float)pos * (1.0f / 512.0f) * log2f(sv));
        float invf = exp2f(-(float)cp * (L2_1E4 / 512.0f));
        float s, c;
        sincosf((float)pos * invf, &s, &c);
        g_xt[idx] = make_float4(c * sc, s * sc, c / sc, s / sc);
    }
}

// transpose W[k][n] -> Wt[n][k] fp16, all three weights (z selects)
__global__ __launch_bounds__(256) void wt_kernel(const float* __restrict__ WQ,
                                                 const float* __restrict__ WK,
                                                 const float* __restrict__ WV) {
    __shared__ float ts[32][33];
    const int S = blockIdx.z;
    const float* W = (S == 0) ? WQ : (S == 1 ? WK : WV);
    int n0 = blockIdx.x * 32, k0 = blockIdx.y * 32;
    int tx = threadIdx.x & 31, ty = threadIdx.x >> 5;
#pragma unroll
    for (int j = 0; j < 4; ++j)
        ts[ty + 8 * j][tx] = W[(size_t)(k0 + ty + 8 * j) * D_ + n0 + tx];
    __syncthreads();
#pragma unroll
    for (int j = 0; j < 4; ++j)
        g_W16[S][(size_t)(n0 + ty + 8 * j) * D_ + k0 + tx] =
            __float2half_rn(ts[tx][ty + 8 * j]);
}

// --------------- fused projection GEMM: z = 0:Q, 1:K, 2:V(->V^T) -------------
__global__ __launch_bounds__(256) void proj_mm() {
    extern __shared__ uint16_t dsm[];
    uint32_t smb = smem_u32(dsm);
    float acc[2][8][4] = {};
    const int t = threadIdx.x;
    const int MODE = blockIdx.z;
    const int n0 = blockIdx.x << 7, m0 = blockIdx.y << 7;

    gemm_loop1(acc,
               g_X16 + (size_t)m0 * D_,
               g_W16[MODE] + (size_t)n0 * D_,
               D_, D_, D_ / 64, smb, t);

    const int lane = t & 31, w = t >> 5;
    const int wm0 = (w >> 1) << 5, wn0 = (w & 1) << 6;
    const int rf = lane >> 2, cf = (lane & 3) << 1;

    if (MODE == 2) {
        // ---- V: write transposed directly to g_T16[d][l] via smem staging ----
#pragma unroll
        for (int i = 0; i < 2; ++i)
#pragma unroll
            for (int hf = 0; hf < 2; ++hf) {
                int r = wm0 + i * 16 + rf + hf * 8;
#pragma unroll
                for (int j = 0; j < 8; ++j) {
                    int c = wn0 + j * 8 + cf;
                    dsm[(uint32_t)c * 136 + r] =
                        (uint16_t)__half_as_ushort(__float2half_rn(acc[i][j][hf * 2]));
                    dsm[(uint32_t)(c + 1) * 136 + r] =
                        (uint16_t)__half_as_ushort(__float2half_rn(acc[i][j][hf * 2 + 1]));
                }
            }
        __syncthreads();
        const int b = m0 >> 11;
        const int l0 = m0 & (L_ - 1);
        __half* T = g_T16 + (size_t)b * L_ * D_;
#pragma unroll
        for (int it = 0; it < 8; ++it) {
            int idx = t + it * 256;
            int c = idx >> 4;                 // local feature 0..127
            int sg = (idx & 15) << 3;         // local row segment
            float4 v = *reinterpret_cast<const float4*>(dsm + (uint32_t)c * 136 + sg);
            *reinterpret_cast<float4*>(T + (size_t)(n0 + c) * L_ + l0 + sg) = v;
        }
        return;
    }

    // ---- Q / K: xPos rotation epilogue ----
    __half* dst = (MODE == 0) ? g_Q16 : g_K16;
#pragma unroll
    for (int i = 0; i < 2; ++i)
#pragma unroll
        for (int hf = 0; hf < 2; ++hf) {
            int row = m0 + wm0 + i * 16 + rf + hf * 8;
            int pos = row & (L_ - 1);
#pragma unroll
            for (int j = 0; j < 8; ++j) {
                int col = n0 + wn0 + j * 8 + cf;
                float x0 = acc[i][j][hf * 2], x1 = acc[i][j][hf * 2 + 1];
                float4 tb = g_xt[(size_t)pos * 512 + (col >> 1)];
                float c = (MODE == 0) ? tb.x : tb.z;
                float s = (MODE == 0) ? tb.y : tb.w;
                float y0 = x0 * c - x1 * s;
                float y1 = x1 * c + x0 * s;
                __half2 hv = __floats2half2_rn(y0, y1);
                *reinterpret_cast<__half2*>(dst + (size_t)row * D_ + col) = hv;
            }
        }
}

// -------------------- A = (Q K^T) * decay, fp16 (window tiles only) ----------
__global__ __launch_bounds__(256) void qk_mm() {
    extern __shared__ uint16_t dsm[];
    uint32_t smb = smem_u32(dsm);
    __shared__ float pw[128], ipw[128];
    const int t = threadIdx.x;
    const int b = blockIdx.z;
    const int nt = blockIdx.y;                 // query tile
    const int mt = nt - 4 + (int)blockIdx.x;   // key tile within window
    if (mt < 0) return;
    const int n0 = nt << 7, m0 = mt << 7;

    if (t < 128) {
        pw[t] = exp2f((float)t * LOG2G);
        ipw[t] = exp2f(-(float)t * LOG2G);
    }

    float acc[2][8][4] = {};
    gemm_loop1(acc,
               g_Q16 + (size_t)(b * L_ + n0) * D_,
               g_K16 + (size_t)(b * L_ + m0) * D_,
               D_, D_, D_ / 64, smb, t);

    const int lane = t & 31, w = t >> 5;
    const int wm0 = (w >> 1) << 5, wn0 = (w & 1) << 6;
    const int rf = lane >> 2, cf = (lane & 3) << 1;
    const float base = exp2f((float)(n0 - m0) * LOG2G);
    __half* A = g_A + (size_t)b * L_ * L_;

#pragma unroll
    for (int i = 0; i < 2; ++i)
#pragma unroll
        for (int hf = 0; hf < 2; ++hf) {
            int r = wm0 + i * 16 + rf + hf * 8;
            int gn = n0 + r;
            float bp = base * pw[r];
#pragma unroll
            for (int j = 0; j < 8; ++j) {
                int c = wn0 + j * 8 + cf;
                int gm = m0 + c;
                float v0 = (gm <= gn) ? acc[i][j][hf * 2] * (bp * ipw[c]) : 0.f;
                float v1 = (gm + 1 <= gn) ? acc[i][j][hf * 2 + 1] * (bp * ipw[c + 1]) : 0.f;
                __half2 hv = __floats2half2_rn(v0, v1);
                *reinterpret_cast<__half2*>(A + (size_t)gn * L_ + gm) = hv;
            }
        }
}

// ------------------------------ out = A @ V ----------------------------------
__global__ __launch_bounds__(256) void av_mm(float* __restrict__ out) {
    extern __shared__ uint16_t dsm[];
    uint32_t smb = smem_u32(dsm);
    const int t = threadIdx.x;
    const int b = blockIdx.z;
    const int j0 = blockIdx.x << 7;                     // output features
    const int n0 = ((int)gridDim.y - 1 - (int)blockIdx.y) << 7;  // heavy tiles first
    const int start = (n0 > WIN) ? (n0 - WIN) : 0;      // decay-truncated key start
    const int nch = (n0 + 128 - start) >> 6;

    float acc[2][8][4] = {};
    gemm_loop1(acc,
               g_A + ((size_t)b * L_ + n0) * L_ + start,
               g_T16 + (size_t)b * L_ * D_ + (size_t)j0 * L_ + start,
               L_, L_, nch, smb, t);

    const int lane = t & 31, w = t >> 5;
    const int wm0 = (w >> 1) << 5, wn0 = (w & 1) << 6;
    const int rf = lane >> 2, cf = (lane & 3) << 1;

#pragma unroll
    for (int i = 0; i < 2; ++i)
#pragma unroll
        for (int hf = 0; hf < 2; ++hf) {
            int row = n0 + wm0 + i * 16 + rf + hf * 8;
#pragma unroll
            for (int j = 0; j < 8; ++j) {
                int col = j0 + wn0 + j * 8 + cf;
                float2 v;
                v.x = acc[i][j][hf * 2];
                v.y = acc[i][j][hf * 2 + 1];
                *reinterpret_cast<float2*>(out + ((size_t)(b * L_ + row)) * D_ + col) = v;
            }
        }
}

// -----------------------------------------------------------------------------
extern "C" void kernel_launch(void* const* d_in, const int* in_sizes, int n_in,
                              void* d_out, int out_size) {
    const float* X = (const float*)d_in[0];
    const float* WQ = (const float*)d_in[1];
    const float* WK = (const float*)d_in[2];
    const float* WV = (const float*)d_in[3];
    float* out = (float*)d_out;

    cudaFuncSetAttribute(proj_mm, cudaFuncAttributeMaxDynamicSharedMemorySize, GEMM_SMEM);
    cudaFuncSetAttribute(qk_mm, cudaFuncAttributeMaxDynamicSharedMemorySize, GEMM_SMEM);
    cudaFuncSetAttribute(av_mm, cudaFuncAttributeMaxDynamicSharedMemorySize, GEMM_SMEM);

    prep_kernel<<<(NBL * D_) / 1024 + (L_ * 512) / 256, 256>>>(X);
    wt_kernel<<<dim3(32, 32, 3), 256>>>(WQ, WK, WV);
    proj_mm<<<dim3(8, 64, 3), 256, GEMM_SMEM>>>();
    qk_mm<<<dim3(5, 16, B_), 256, GEMM_SMEM>>>();
    av_mm<<<dim3(8, 16, B_), 256, GEMM_SMEM>>>(out);
}